// round 14
// baseline (speedup 1.0000x reference)
#include <cuda_runtime.h>
#include <cuda_fp16.h>
#include <cstdint>
#include <math.h>

#define B_SZ   4
#define NLEN   4128
#define DIMN   1024
#define HEADS  16
#define BLKLEN 129
#define NB     32
#define DK     64
#define TOK    (B_SZ * NLEN)   // 16512

// ---------------- scratch (device globals: allocation-free) ----------------
__device__ __half g_x16[TOK * DIMN];
__device__ __half g_q16[TOK * DIMN];
__device__ __half g_k16[TOK * DIMN];
__device__ __half g_v16[TOK * DIMN];
__device__ __half g_a16[TOK * DIMN];
__device__ __half g_w16[4 * DIMN * DIMN];

// ============================ helpers ======================================
__device__ __forceinline__ uint32_t smem_u32(const void* p) {
    return (uint32_t)__cvta_generic_to_shared(p);
}
__device__ __forceinline__ void cp16(uint32_t d, const void* s) {
    asm volatile("cp.async.cg.shared.global [%0], [%1], 16;\n" :: "r"(d), "l"(s));
}
__device__ __forceinline__ void cp_commit() {
    asm volatile("cp.async.commit_group;\n");
}
template<int N_> __device__ __forceinline__ void cpwait() {
    asm volatile("cp.async.wait_group %0;\n" :: "n"(N_));
}
__device__ __forceinline__ void ldm_x4(uint32_t* r, uint32_t a) {
    asm volatile("ldmatrix.sync.aligned.m8n8.x4.shared.b16 {%0,%1,%2,%3}, [%4];\n"
                 : "=r"(r[0]), "=r"(r[1]), "=r"(r[2]), "=r"(r[3]) : "r"(a));
}
__device__ __forceinline__ void ldm_x4_t(uint32_t* r, uint32_t a) {
    asm volatile("ldmatrix.sync.aligned.m8n8.x4.trans.shared.b16 {%0,%1,%2,%3}, [%4];\n"
                 : "=r"(r[0]), "=r"(r[1]), "=r"(r[2]), "=r"(r[3]) : "r"(a));
}
__device__ __forceinline__ void mma_h(float* d, const uint32_t* a,
                                      uint32_t b0, uint32_t b1) {
    asm volatile("mma.sync.aligned.m16n8k16.row.col.f32.f16.f16.f32 "
                 "{%0,%1,%2,%3}, {%4,%5,%6,%7}, {%8,%9}, {%0,%1,%2,%3};\n"
                 : "+f"(d[0]), "+f"(d[1]), "+f"(d[2]), "+f"(d[3])
                 : "r"(a[0]), "r"(a[1]), "r"(a[2]), "r"(a[3]), "r"(b0), "r"(b1));
}
__device__ __forceinline__ uint32_t packh2(float x, float y) {
    __half2 h = __floats2half2_rn(x, y);
    return *(uint32_t*)&h;
}

// ---------------------------------------------------------------------------
// conversions
// ---------------------------------------------------------------------------
__global__ void cvt_h4(const float4* __restrict__ in, __half2* __restrict__ out, int n4)
{
    int i = blockIdx.x * blockDim.x + threadIdx.x;
    if (i >= n4) return;
    float4 x = in[i];
    out[2 * i + 0] = __floats2half2_rn(x.x, x.y);
    out[2 * i + 1] = __floats2half2_rn(x.z, x.w);
}

__global__ void cvt_w4(const float4* __restrict__ W0, const float4* __restrict__ W1,
                       const float4* __restrict__ W2, const float4* __restrict__ W3,
                       __half2* __restrict__ out, int n4)
{
    const int z = blockIdx.y;
    const float4* src = (z == 0) ? W0 : (z == 1) ? W1 : (z == 2) ? W2 : W3;
    __half2* dst = out + (size_t)z * (DIMN * DIMN / 2);
    int i = blockIdx.x * blockDim.x + threadIdx.x;
    if (i >= n4) return;
    float4 x = src[i];
    dst[2 * i + 0] = __floats2half2_rn(x.x, x.y);
    dst[2 * i + 1] = __floats2half2_rn(x.z, x.w);
}

// ---------------------------------------------------------------------------
// Single-term fp16 HMMA GEMM core: C[M,N] = A[M,K] @ B[N,K]^T
// BM=64, BN=128, BK=32, 3-stage cp.async, 4 warps (2m x 2n, 32x64 warptile),
// 128 threads, 4 CTAs/SM.
// ---------------------------------------------------------------------------
#define SSTRIDE 40
#define TILE_A  (64 * SSTRIDE * 2)    // 5120 B
#define TILE_BB (128 * SSTRIDE * 2)   // 10240 B
#define STAGE_B (TILE_A + TILE_BB)    // 15360 B
#define GEMM_SMEM (3 * STAGE_B)       // 46080 B
#define KT32 (DIMN / 32)              // 32

__device__ __forceinline__ void gemm_core(
    const __half* pA, const __half* pB,
    uint32_t dstA, uint32_t dstB, uint32_t aoff, uint32_t boff,
    float acc[2][8][4])
{
    // per-thread loader mapping (128 threads):
    //   A: 64 rows x 32 cols; 2 threads/row, 32B each  -> 2 cp16
    //   B: 128 rows x 32 cols; 1 thread/row, 64B each  -> 4 cp16
#define PREF(kt, st) do {                                                   \
        const uint32_t db = (uint32_t)(st) * STAGE_B;                       \
        const __half* sA = pA + (kt) * 32;                                  \
        const __half* sB = pB + (kt) * 32;                                  \
        cp16(dstA + db,      sA);      cp16(dstA + db + 16, sA + 8);        \
        cp16(dstB + db,      sB);      cp16(dstB + db + 16, sB + 8);        \
        cp16(dstB + db + 32, sB + 16); cp16(dstB + db + 48, sB + 24);       \
        cp_commit();                                                        \
    } while (0)

    PREF(0, 0);
    PREF(1, 1);
    for (int kt = 0; kt < KT32; kt++) {
        const int st = kt % 3;
        if (kt + 2 < KT32)      { PREF(kt + 2, (kt + 2) % 3); cpwait<2>(); }
        else if (kt + 1 < KT32) { cpwait<1>(); }
        else                    { cpwait<0>(); }
        __syncthreads();

        const uint32_t sb = (uint32_t)st * STAGE_B;
#pragma unroll
        for (int kk = 0; kk < 2; kk++) {
            const uint32_t ko = sb + kk * 32;
            uint32_t a[2][4], b[8][2];
            ldm_x4(a[0], aoff + ko);
            ldm_x4(a[1], aoff + ko + 16 * SSTRIDE * 2);
#pragma unroll
            for (int ng = 0; ng < 4; ng++) {
                uint32_t r[4];
                ldm_x4(r, boff + ko + ng * 16 * SSTRIDE * 2);
                b[2 * ng][0] = r[0]; b[2 * ng][1] = r[2];
                b[2 * ng + 1][0] = r[1]; b[2 * ng + 1][1] = r[3];
            }
#pragma unroll
            for (int mt = 0; mt < 2; mt++)
#pragma unroll
                for (int nt = 0; nt < 8; nt++)
                    mma_h(acc[mt][nt], a[mt], b[nt][0], b[nt][1]);
        }
        __syncthreads();
    }
#undef PREF
}

// fused QKV: z selects weight + fp16 output
__global__ __launch_bounds__(128, 4)
void gemm_qkv(const __half* __restrict__ A,
              const __half* __restrict__ W0, const __half* __restrict__ W1,
              const __half* __restrict__ W2,
              __half* __restrict__ O0, __half* __restrict__ O1,
              __half* __restrict__ O2)
{
    extern __shared__ __half smemh[];
    const uint32_t smem = smem_u32(smemh);
    const int tid = threadIdx.x, lane = tid & 31, w = tid >> 5;
    const int m0 = blockIdx.y * 64, n0 = blockIdx.x * 128;
    const __half* Bm = (blockIdx.z == 0) ? W0 : (blockIdx.z == 1 ? W1 : W2);
    __half* C = (blockIdx.z == 0) ? O0 : (blockIdx.z == 1 ? O1 : O2);

    // loader pointers
    const int lrA = tid & 63, lcA = (tid >> 6) * 16;       // halfs
    const __half* pA = A  + (size_t)(m0 + lrA) * DIMN + lcA;
    const __half* pB = Bm + (size_t)(n0 + tid) * DIMN;
    const uint32_t dstA = smem + (uint32_t)(lrA * SSTRIDE + lcA) * 2;
    const uint32_t dstB = smem + TILE_A + (uint32_t)(tid * SSTRIDE) * 2;

    // compute mapping: 4 warps = 2 (M) x 2 (N), warptile 32x64
    const int wm = w & 1, wn = w >> 1;
    const uint32_t aoff = smem +
        (uint32_t)((wm * 32 + (lane & 15)) * SSTRIDE + (lane >> 4) * 8) * 2;
    const uint32_t boff = smem + TILE_A +
        (uint32_t)((wn * 64 + (lane & 15)) * SSTRIDE + (lane >> 4) * 8) * 2;

    float acc[2][8][4];
#pragma unroll
    for (int i = 0; i < 2; i++)
#pragma unroll
        for (int j = 0; j < 8; j++)
#pragma unroll
            for (int t = 0; t < 4; t++) acc[i][j][t] = 0.f;

    gemm_core(pA, pB, dstA, dstB, aoff, boff, acc);

    const int gr = lane >> 2, gc = (lane & 3) * 2;
#pragma unroll
    for (int mt = 0; mt < 2; mt++) {
        const int row = m0 + wm * 32 + mt * 16 + gr;
#pragma unroll
        for (int nt = 0; nt < 8; nt++) {
            const int col = n0 + wn * 64 + nt * 8 + gc;
            *(__half2*)(C + (size_t)row * DIMN + col) =
                __floats2half2_rn(acc[mt][nt][0], acc[mt][nt][1]);
            *(__half2*)(C + (size_t)(row + 8) * DIMN + col) =
                __floats2half2_rn(acc[mt][nt][2], acc[mt][nt][3]);
        }
    }
}

// final GEMM: fp32 out + bias
__global__ __launch_bounds__(128, 4)
void gemm_out(const __half* __restrict__ A, const __half* __restrict__ Bm,
              const float* __restrict__ bias, float* __restrict__ C)
{
    extern __shared__ __half smemh[];
    const uint32_t smem = smem_u32(smemh);
    const int tid = threadIdx.x, lane = tid & 31, w = tid >> 5;
    const int m0 = blockIdx.y * 64, n0 = blockIdx.x * 128;

    const int lrA = tid & 63, lcA = (tid >> 6) * 16;
    const __half* pA = A  + (size_t)(m0 + lrA) * DIMN + lcA;
    const __half* pB = Bm + (size_t)(n0 + tid) * DIMN;
    const uint32_t dstA = smem + (uint32_t)(lrA * SSTRIDE + lcA) * 2;
    const uint32_t dstB = smem + TILE_A + (uint32_t)(tid * SSTRIDE) * 2;

    const int wm = w & 1, wn = w >> 1;
    const uint32_t aoff = smem +
        (uint32_t)((wm * 32 + (lane & 15)) * SSTRIDE + (lane >> 4) * 8) * 2;
    const uint32_t boff = smem + TILE_A +
        (uint32_t)((wn * 64 + (lane & 15)) * SSTRIDE + (lane >> 4) * 8) * 2;

    float acc[2][8][4];
#pragma unroll
    for (int i = 0; i < 2; i++)
#pragma unroll
        for (int j = 0; j < 8; j++)
#pragma unroll
            for (int t = 0; t < 4; t++) acc[i][j][t] = 0.f;

    gemm_core(pA, pB, dstA, dstB, aoff, boff, acc);

    const int gr = lane >> 2, gc = (lane & 3) * 2;
#pragma unroll
    for (int mt = 0; mt < 2; mt++) {
        const int row = m0 + wm * 32 + mt * 16 + gr;
#pragma unroll
        for (int nt = 0; nt < 8; nt++) {
            const int col = n0 + wn * 64 + nt * 8 + gc;
            const float b0 = bias[col], b1 = bias[col + 1];
            *(float2*)(C + (size_t)row * DIMN + col) =
                make_float2(acc[mt][nt][0] + b0, acc[mt][nt][1] + b1);
            *(float2*)(C + (size_t)(row + 8) * DIMN + col) =
                make_float2(acc[mt][nt][2] + b0, acc[mt][nt][3] + b1);
        }
    }
}

// ---------------------------------------------------------------------------
// HMMA block-local attention + fused global attention (proven R7 version).
// One CTA per (b, blk, head), 8 warps x 16 query rows (warp 7 takes tile 8).
// ---------------------------------------------------------------------------
#define AQS 72                               // smem row stride (halfs)
#define HQ  (144 * AQS)                      // halfs per tile
#define GK_OFF (3 * HQ)
#define GV_OFF (GK_OFF + 32 * AQS)
#define GP_BYTE ((GV_OFF + 32 * AQS) * 2)
#define GOUT_BYTE (GP_BYTE + 32 * 4)
#define AT_SMEM (GOUT_BYTE + 64 * 4)         // 71808 B

__global__ __launch_bounds__(256, 2)
void blk_attn_tc(const __half* __restrict__ q16, const __half* __restrict__ k16,
                 const __half* __restrict__ v16, __half* __restrict__ a16)
{
    extern __shared__ __half sh[];
    __half* Qs = sh;
    __half* Ks = sh + HQ;
    __half* Vs = sh + 2 * HQ;
    __half* gk = sh + GK_OFF;
    __half* gv = sh + GV_OFF;
    float* gp   = (float*)((char*)sh + GP_BYTE);
    float* gout = (float*)((char*)sh + GOUT_BYTE);

    const int bid = blockIdx.x;
    const int h = bid & 15, blk = (bid >> 4) & 31, b = bid >> 9;
    const size_t gbase = ((size_t)(b * NLEN + blk * BLKLEN)) * DIMN + h * DK;
    const int tid = threadIdx.x, lane = tid & 31, wid = tid >> 5;

    const uint4 z4 = make_uint4(0, 0, 0, 0);
    for (int i = tid; i < 360; i += 256) {
        const int t = i / 120, j = i % 120;
        const int r = 129 + (j >> 3), c = (j & 7) * 8;
        __half* base = (t == 0) ? Qs : (t == 1) ? Ks : Vs;
        *(uint4*)&base[r * AQS + c] = z4;
    }
    for (int i = tid; i < 1032; i += 256) {
        const int r = i >> 3, c = (i & 7) * 8;
        const uint32_t so = (uint32_t)(r * AQS + c) * 2;
        const size_t g = gbase + (size_t)r * DIMN + c;
        cp16(smem_u32(Qs) + so, q16 + g);
        cp16(smem_u32(Ks) + so, k16 + g);
        cp16(smem_u32(Vs) + so, v16 + g);
    }
    {
        const int r = tid >> 3, c = (tid & 7) * 8;
        const size_t g = ((size_t)(b * NLEN + r * BLKLEN)) * DIMN + h * DK + c;
        const uint32_t so = (uint32_t)(r * AQS + c) * 2;
        cp16(smem_u32(gk) + so, k16 + g);
        cp16(smem_u32(gv) + so, v16 + g);
    }
    cp_commit();
    cpwait<0>();
    __syncthreads();

    const float scale = 0.125f;

    // warp 0: global attention for this block's first token
    if (wid == 0) {
        float s = 0.f;
#pragma unroll
        for (int i = 0; i < DK / 2; i++) {
            float2 qf = __half22float2(*(const __half2*)&Qs[2 * i]);
            float2 kf = __half22float2(*(const __half2*)&gk[lane * AQS + 2 * i]);
            s += qf.x * kf.x + qf.y * kf.y;
        }
        float p = __expf(s * scale);
        float lsum = p;
#pragma unroll
        for (int d = 1; d < 32; d <<= 1)
            lsum += __shfl_xor_sync(0xFFFFFFFFu, lsum, d);
        gp[lane] = p;
        __syncwarp();
        const float inv = 1.0f / lsum;
        float o0 = 0.f, o1 = 0.f;
#pragma unroll
        for (int k = 0; k < NB; k++) {
            const float pk = gp[k];
            float2 vf = __half22float2(*(const __half2*)&gv[k * AQS + 2 * lane]);
            o0 += pk * vf.x; o1 += pk * vf.y;
        }
        gout[2 * lane]     = o0 * inv;
        gout[2 * lane + 1] = o1 * inv;
        __syncwarp();
    }

    const int cbase = (lane & 3) * 2;
    const int gr = lane >> 2;
    const uint32_t loff = (uint32_t)((lane & 15) * AQS + (lane >> 4) * 8) * 2;
    const int vmat = lane >> 3;
    const uint32_t vb = smem_u32(Vs) +
        (uint32_t)(((vmat & 1) * 8 + (lane & 7)) * AQS + (vmat >> 1) * 8) * 2;

    const int niter = (wid == 7) ? 2 : 1;
    for (int it = 0; it < niter; it++) {
        const int t = (it == 0) ? wid : 8;
        const int m0 = t * 16;

        uint32_t aq[4][4];
        {
            const uint32_t qb = smem_u32(Qs) + (uint32_t)(m0 * AQS) * 2 + loff;
#pragma unroll
            for (int ks = 0; ks < 4; ks++) ldm_x4(aq[ks], qb + ks * 32);
        }

        uint32_t P2[17][2];
        float l0 = 0.f, l1 = 0.f;
        const uint32_t kb = smem_u32(Ks) + loff;
#pragma unroll
        for (int jp = 0; jp < 8; jp++) {
            float e0[4] = {0.f, 0.f, 0.f, 0.f};
            float e1[4] = {0.f, 0.f, 0.f, 0.f};
            const uint32_t kjb = kb + (uint32_t)(jp * 16 * AQS) * 2;
#pragma unroll
            for (int ks = 0; ks < 4; ks++) {
                uint32_t r[4];
                ldm_x4(r, kjb + ks * 32);
                mma_h(e0, aq[ks], r[0], r[2]);
                mma_h(e1, aq[ks], r[1], r[3]);
            }
            float p00 = __expf(e0[0] * scale), p01 = __expf(e0[1] * scale);
            float p02 = __expf(e0[2] * scale), p03 = __expf(e0[3] * scale);
            float p10 = __expf(e1[0] * scale), p11 = __expf(e1[1] * scale);
            float p12 = __expf(e1[2] * scale), p13 = __expf(e1[3] * scale);
            l0 += (p00 + p01) + (p10 + p11);
            l1 += (p02 + p03) + (p12 + p13);
            P2[2 * jp][0] = packh2(p00, p01);
            P2[2 * jp][1] = packh2(p02, p03);
            P2[2 * jp + 1][0] = packh2(p10, p11);
            P2[2 * jp + 1][1] = packh2(p12, p13);
        }
        {
            float e0[4] = {0.f, 0.f, 0.f, 0.f};
            const uint32_t kjb = kb + (uint32_t)(128 * AQS) * 2;
#pragma unroll
            for (int ks = 0; ks < 4; ks++) {
                uint32_t r[4];
                ldm_x4(r, kjb + ks * 32);
                mma_h(e0, aq[ks], r[0], r[2]);
            }
            const bool v = (cbase == 0);
            float p0 = v ? __expf(e0[0] * scale) : 0.f;
            float p2 = v ? __expf(e0[2] * scale) : 0.f;
            l0 += p0; l1 += p2;
            P2[16][0] = packh2(p0, 0.f);
            P2[16][1] = packh2(p2, 0.f);
        }
        l0 += __shfl_xor_sync(0xFFFFFFFFu, l0, 1);
        l0 += __shfl_xor_sync(0xFFFFFFFFu, l0, 2);
        l1 += __shfl_xor_sync(0xFFFFFFFFu, l1, 1);
        l1 += __shfl_xor_sync(0xFFFFFFFFu, l1, 2);

        float oacc[8][4];
#pragma unroll
        for (int g = 0; g < 8; g++)
#pragma unroll
            for (int u = 0; u < 4; u++) oacc[g][u] = 0.f;

#pragma unroll
        for (int kp = 0; kp < 9; kp++) {
            uint32_t pa[4];
            pa[0] = P2[2 * kp][0];
            pa[1] = P2[2 * kp][1];
            if (kp < 8) { pa[2] = P2[2 * kp + 1][0]; pa[3] = P2[2 * kp + 1][1]; }
            else        { pa[2] = 0u; pa[3] = 0u; }
            const uint32_t vkb = vb + (uint32_t)(kp * 16 * AQS) * 2;
#pragma unroll
            for (int g = 0; g < 4; g++) {
                uint32_t r[4];
                ldm_x4_t(r, vkb + g * 32);
                mma_h(oacc[2 * g],     pa, r[0], r[1]);
                mma_h(oacc[2 * g + 1], pa, r[2], r[3]);
            }
        }

        const float rl0 = 1.0f / l0, rl1 = 1.0f / l1;
        const int r0 = m0 + gr, r1 = r0 + 8;
#pragma unroll
        for (int g = 0; g < 8; g++) {
            const int col = g * 8 + cbase;
            float o0 = oacc[g][0] * rl0, o1 = oacc[g][1] * rl0;
            float o2 = oacc[g][2] * rl1, o3 = oacc[g][3] * rl1;
            if (r0 == 0) { o0 += gout[col]; o1 += gout[col + 1]; }
            if (r0 < BLKLEN)
                *(__half2*)(a16 + gbase + (size_t)r0 * DIMN + col) =
                    __floats2half2_rn(o0, o1);
            if (r1 < BLKLEN)
                *(__half2*)(a16 + gbase + (size_t)r1 * DIMN + col) =
                    __floats2half2_rn(o2, o3);
        }
    }
}

// ---------------------------------------------------------------------------
extern "C" void kernel_launch(void* const* d_in, const int* in_sizes, int n_in,
                              void* d_out, int out_size)
{
    const float* x  = (const float*)d_in[0];
    const float* Wq = (const float*)d_in[1];
    const float* Wk = (const float*)d_in[2];
    const float* Wv = (const float*)d_in[3];
    const float* Wo = (const float*)d_in[4];
    const float* bo = (const float*)d_in[5];
    float* out = (float*)d_out;

    __half *x16, *q16, *k16, *v16, *a16, *w16;
    cudaGetSymbolAddress((void**)&x16, g_x16);
    cudaGetSymbolAddress((void**)&q16, g_q16);
    cudaGetSymbolAddress((void**)&k16, g_k16);
    cudaGetSymbolAddress((void**)&v16, g_v16);
    cudaGetSymbolAddress((void**)&a16, g_a16);
    cudaGetSymbolAddress((void**)&w16, g_w16);

    cudaFuncSetAttribute(gemm_qkv, cudaFuncAttributeMaxDynamicSharedMemorySize, GEMM_SMEM);
    cudaFuncSetAttribute(gemm_out, cudaFuncAttributeMaxDynamicSharedMemorySize, GEMM_SMEM);
    cudaFuncSetAttribute(blk_attn_tc, cudaFuncAttributeMaxDynamicSharedMemorySize, AT_SMEM);

    const int W = DIMN * DIMN;
    const int n4x = TOK * DIMN / 4;
    const int n4w = W / 4;

    cvt_h4<<<(n4x + 255) / 256, 256>>>((const float4*)x, (__half2*)x16, n4x);
    dim3 gW((n4w + 255) / 256, 4);
    cvt_w4<<<gW, 256>>>((const float4*)Wq, (const float4*)Wk,
                        (const float4*)Wv, (const float4*)Wo,
                        (__half2*)w16, n4w);

    dim3 gQKV(DIMN / 128, TOK / 64, 3);    // (8, 258, 3)
    gemm_qkv<<<gQKV, 128, GEMM_SMEM>>>(x16,
        w16 + 0 * W, w16 + 1 * W, w16 + 2 * W, q16, k16, v16);

    blk_attn_tc<<<B_SZ * NB * HEADS, 256, AT_SMEM>>>(q16, k16, v16, a16);

    dim3 gO(DIMN / 128, TOK / 64);         // (8, 258)
    gemm_out<<<gO, 128, GEMM_SMEM>>>(a16, w16 + 3 * W, bo, out);
}

// round 15
// speedup vs baseline: 1.1414x; 1.1414x over previous
#include <cuda_runtime.h>
#include <cuda_fp16.h>
#include <cstdint>
#include <math.h>

#define B_SZ   4
#define NLEN   4128
#define DIMN   1024
#define HEADS  16
#define BLKLEN 129
#define NB     32
#define DK     64
#define TOK    (B_SZ * NLEN)   // 16512

// ---------------- scratch (device globals: allocation-free) ----------------
__device__ __half g_x16[TOK * DIMN];
__device__ __half g_q16[TOK * DIMN];
__device__ __half g_k16[TOK * DIMN];
__device__ __half g_v16[TOK * DIMN];
__device__ __half g_a16[TOK * DIMN];
__device__ __half g_w16[4 * DIMN * DIMN];

// ============================ helpers ======================================
__device__ __forceinline__ uint32_t smem_u32(const void* p) {
    return (uint32_t)__cvta_generic_to_shared(p);
}
__device__ __forceinline__ void cp16(uint32_t d, const void* s) {
    asm volatile("cp.async.cg.shared.global [%0], [%1], 16;\n" :: "r"(d), "l"(s));
}
__device__ __forceinline__ void cp_commit() {
    asm volatile("cp.async.commit_group;\n");
}
template<int N_> __device__ __forceinline__ void cpwait() {
    asm volatile("cp.async.wait_group %0;\n" :: "n"(N_));
}
__device__ __forceinline__ void ldm_x4(uint32_t* r, uint32_t a) {
    asm volatile("ldmatrix.sync.aligned.m8n8.x4.shared.b16 {%0,%1,%2,%3}, [%4];\n"
                 : "=r"(r[0]), "=r"(r[1]), "=r"(r[2]), "=r"(r[3]) : "r"(a));
}
__device__ __forceinline__ void ldm_x4_t(uint32_t* r, uint32_t a) {
    asm volatile("ldmatrix.sync.aligned.m8n8.x4.trans.shared.b16 {%0,%1,%2,%3}, [%4];\n"
                 : "=r"(r[0]), "=r"(r[1]), "=r"(r[2]), "=r"(r[3]) : "r"(a));
}
__device__ __forceinline__ void mma_h(float* d, const uint32_t* a,
                                      uint32_t b0, uint32_t b1) {
    asm volatile("mma.sync.aligned.m16n8k16.row.col.f32.f16.f16.f32 "
                 "{%0,%1,%2,%3}, {%4,%5,%6,%7}, {%8,%9}, {%0,%1,%2,%3};\n"
                 : "+f"(d[0]), "+f"(d[1]), "+f"(d[2]), "+f"(d[3])
                 : "r"(a[0]), "r"(a[1]), "r"(a[2]), "r"(a[3]), "r"(b0), "r"(b1));
}
__device__ __forceinline__ uint32_t packh2(float x, float y) {
    __half2 h = __floats2half2_rn(x, y);
    return *(uint32_t*)&h;
}

// ---------------------------------------------------------------------------
// conversions
// ---------------------------------------------------------------------------
__global__ void cvt_h4(const float4* __restrict__ in, __half2* __restrict__ out, int n4)
{
    int i = blockIdx.x * blockDim.x + threadIdx.x;
    if (i >= n4) return;
    float4 x = in[i];
    out[2 * i + 0] = __floats2half2_rn(x.x, x.y);
    out[2 * i + 1] = __floats2half2_rn(x.z, x.w);
}

__global__ void cvt_w4(const float4* __restrict__ W0, const float4* __restrict__ W1,
                       const float4* __restrict__ W2, const float4* __restrict__ W3,
                       __half2* __restrict__ out, int n4)
{
    const int z = blockIdx.y;
    const float4* src = (z == 0) ? W0 : (z == 1) ? W1 : (z == 2) ? W2 : W3;
    __half2* dst = out + (size_t)z * (DIMN * DIMN / 2);
    int i = blockIdx.x * blockDim.x + threadIdx.x;
    if (i >= n4) return;
    float4 x = src[i];
    dst[2 * i + 0] = __floats2half2_rn(x.x, x.y);
    dst[2 * i + 1] = __floats2half2_rn(x.z, x.w);
}

// ---------------------------------------------------------------------------
// Single-term fp16 HMMA GEMM core: C[M,N] = A[M,K] @ B[N,K]^T
// BM=BN=128, BK=64, 3-stage cp.async, 8 warps (4m x 2n), 2 CTAs/SM.
// ---------------------------------------------------------------------------
#define SSTRIDE 72                     // halfs per smem row (144 B)
#define TILE_B (128 * SSTRIDE * 2)     // 18432 B
#define STAGE_B (2 * TILE_B)           // 36864 B
#define GEMM_SMEM (3 * STAGE_B)        // 110592 B
#define KT64 (DIMN / 64)               // 16

__device__ __forceinline__ void gemm_core(
    const __half* pA, const __half* pB,
    uint32_t dst0, uint32_t aoff, uint32_t boff,
    float acc[2][8][4])
{
    // loader: 2 threads/row, each 64 B contiguous (4 cp16) per tensor
#define PREF(kt, st) do {                                                   \
        uint32_t db = dst0 + (uint32_t)(st) * STAGE_B;                      \
        const __half* s0 = pA + (kt) * 64;                                  \
        const __half* s1 = pB + (kt) * 64;                                  \
        cp16(db,              s0);      cp16(db + 16,          s0 + 8);     \
        cp16(db + 32,         s0 + 16); cp16(db + 48,          s0 + 24);    \
        cp16(db + TILE_B,     s1);      cp16(db + TILE_B + 16, s1 + 8);     \
        cp16(db + TILE_B + 32, s1 + 16); cp16(db + TILE_B + 48, s1 + 24);   \
        cp_commit();                                                        \
    } while (0)

    PREF(0, 0);
    PREF(1, 1);
    for (int kt = 0; kt < KT64; kt++) {
        const int st = kt % 3;
        if (kt + 2 < KT64)      { PREF(kt + 2, (kt + 2) % 3); cpwait<2>(); }
        else if (kt + 1 < KT64) { cpwait<1>(); }
        else                    { cpwait<0>(); }
        __syncthreads();

        const uint32_t sb = (uint32_t)st * STAGE_B;
#pragma unroll
        for (int kk = 0; kk < 4; kk++) {
            const uint32_t ko = sb + kk * 32;     // 16 halfs = 32 B
            uint32_t a[2][4], b[8][2];
            ldm_x4(a[0], aoff + ko);
            ldm_x4(a[1], aoff + ko + 16 * SSTRIDE * 2);
#pragma unroll
            for (int ng = 0; ng < 4; ng++) {
                uint32_t r[4];
                ldm_x4(r, boff + ko + ng * 16 * SSTRIDE * 2);
                b[2 * ng][0] = r[0]; b[2 * ng][1] = r[2];
                b[2 * ng + 1][0] = r[1]; b[2 * ng + 1][1] = r[3];
            }
#pragma unroll
            for (int mt = 0; mt < 2; mt++)
#pragma unroll
                for (int nt = 0; nt < 8; nt++)
                    mma_h(acc[mt][nt], a[mt], b[nt][0], b[nt][1]);
        }
        __syncthreads();
    }
#undef PREF
}

// fused QKV: z selects weight + fp16 output
__global__ __launch_bounds__(256, 2)
void gemm_qkv(const __half* __restrict__ A,
              const __half* __restrict__ W0, const __half* __restrict__ W1,
              const __half* __restrict__ W2,
              __half* __restrict__ O0, __half* __restrict__ O1,
              __half* __restrict__ O2)
{
    extern __shared__ __half smemh[];
    const uint32_t smem = smem_u32(smemh);
    const int tid = threadIdx.x, lane = tid & 31, w = tid >> 5;
    const int m0 = blockIdx.y * 128, n0 = blockIdx.x * 128;
    const __half* Bm = (blockIdx.z == 0) ? W0 : (blockIdx.z == 1 ? W1 : W2);
    __half* C = (blockIdx.z == 0) ? O0 : (blockIdx.z == 1 ? O1 : O2);

    const int lr = tid & 127, lc = (tid >> 7) * 32;   // halfs
    const __half* pA = A  + (size_t)(m0 + lr) * DIMN + lc;
    const __half* pB = Bm + (size_t)(n0 + lr) * DIMN + lc;
    const uint32_t dst0 = smem + (uint32_t)(lr * SSTRIDE + lc) * 2;

    const int wm = w & 3, wn = w >> 2;
    const uint32_t aoff = smem +
        (uint32_t)((wm * 32 + (lane & 15)) * SSTRIDE + (lane >> 4) * 8) * 2;
    const uint32_t boff = smem + TILE_B +
        (uint32_t)((wn * 64 + (lane & 15)) * SSTRIDE + (lane >> 4) * 8) * 2;

    float acc[2][8][4];
#pragma unroll
    for (int i = 0; i < 2; i++)
#pragma unroll
        for (int j = 0; j < 8; j++)
#pragma unroll
            for (int t = 0; t < 4; t++) acc[i][j][t] = 0.f;

    gemm_core(pA, pB, dst0, aoff, boff, acc);

    const int gr = lane >> 2, gc = (lane & 3) * 2;
#pragma unroll
    for (int mt = 0; mt < 2; mt++) {
        const int row = m0 + wm * 32 + mt * 16 + gr;
#pragma unroll
        for (int nt = 0; nt < 8; nt++) {
            const int col = n0 + wn * 64 + nt * 8 + gc;
            *(__half2*)(C + (size_t)row * DIMN + col) =
                __floats2half2_rn(acc[mt][nt][0], acc[mt][nt][1]);
            *(__half2*)(C + (size_t)(row + 8) * DIMN + col) =
                __floats2half2_rn(acc[mt][nt][2], acc[mt][nt][3]);
        }
    }
}

// final GEMM: fp32 out + bias
__global__ __launch_bounds__(256, 2)
void gemm_out(const __half* __restrict__ A, const __half* __restrict__ Bm,
              const float* __restrict__ bias, float* __restrict__ C)
{
    extern __shared__ __half smemh[];
    const uint32_t smem = smem_u32(smemh);
    const int tid = threadIdx.x, lane = tid & 31, w = tid >> 5;
    const int m0 = blockIdx.y * 128, n0 = blockIdx.x * 128;

    const int lr = tid & 127, lc = (tid >> 7) * 32;
    const __half* pA = A  + (size_t)(m0 + lr) * DIMN + lc;
    const __half* pB = Bm + (size_t)(n0 + lr) * DIMN + lc;
    const uint32_t dst0 = smem + (uint32_t)(lr * SSTRIDE + lc) * 2;

    const int wm = w & 3, wn = w >> 2;
    const uint32_t aoff = smem +
        (uint32_t)((wm * 32 + (lane & 15)) * SSTRIDE + (lane >> 4) * 8) * 2;
    const uint32_t boff = smem + TILE_B +
        (uint32_t)((wn * 64 + (lane & 15)) * SSTRIDE + (lane >> 4) * 8) * 2;

    float acc[2][8][4];
#pragma unroll
    for (int i = 0; i < 2; i++)
#pragma unroll
        for (int j = 0; j < 8; j++)
#pragma unroll
            for (int t = 0; t < 4; t++) acc[i][j][t] = 0.f;

    gemm_core(pA, pB, dst0, aoff, boff, acc);

    const int gr = lane >> 2, gc = (lane & 3) * 2;
#pragma unroll
    for (int mt = 0; mt < 2; mt++) {
        const int row = m0 + wm * 32 + mt * 16 + gr;
#pragma unroll
        for (int nt = 0; nt < 8; nt++) {
            const int col = n0 + wn * 64 + nt * 8 + gc;
            const float b0 = bias[col], b1 = bias[col + 1];
            *(float2*)(C + (size_t)row * DIMN + col) =
                make_float2(acc[mt][nt][0] + b0, acc[mt][nt][1] + b1);
            *(float2*)(C + (size_t)(row + 8) * DIMN + col) =
                make_float2(acc[mt][nt][2] + b0, acc[mt][nt][3] + b1);
        }
    }
}

// ---------------------------------------------------------------------------
// HMMA block-local attention + fused global attention (proven R7 version).
// One CTA per (b, blk, head), 8 warps x 16 query rows (warp 7 takes tile 8).
// ---------------------------------------------------------------------------
#define AQS 72                               // smem row stride (halfs)
#define HQ  (144 * AQS)                      // halfs per tile
#define GK_OFF (3 * HQ)
#define GV_OFF (GK_OFF + 32 * AQS)
#define GP_BYTE ((GV_OFF + 32 * AQS) * 2)
#define GOUT_BYTE (GP_BYTE + 32 * 4)
#define AT_SMEM (GOUT_BYTE + 64 * 4)         // 71808 B

__global__ __launch_bounds__(256, 2)
void blk_attn_tc(const __half* __restrict__ q16, const __half* __restrict__ k16,
                 const __half* __restrict__ v16, __half* __restrict__ a16)
{
    extern __shared__ __half sh[];
    __half* Qs = sh;
    __half* Ks = sh + HQ;
    __half* Vs = sh + 2 * HQ;
    __half* gk = sh + GK_OFF;
    __half* gv = sh + GV_OFF;
    float* gp   = (float*)((char*)sh + GP_BYTE);
    float* gout = (float*)((char*)sh + GOUT_BYTE);

    const int bid = blockIdx.x;
    const int h = bid & 15, blk = (bid >> 4) & 31, b = bid >> 9;
    const size_t gbase = ((size_t)(b * NLEN + blk * BLKLEN)) * DIMN + h * DK;
    const int tid = threadIdx.x, lane = tid & 31, wid = tid >> 5;

    const uint4 z4 = make_uint4(0, 0, 0, 0);
    for (int i = tid; i < 360; i += 256) {
        const int t = i / 120, j = i % 120;
        const int r = 129 + (j >> 3), c = (j & 7) * 8;
        __half* base = (t == 0) ? Qs : (t == 1) ? Ks : Vs;
        *(uint4*)&base[r * AQS + c] = z4;
    }
    for (int i = tid; i < 1032; i += 256) {
        const int r = i >> 3, c = (i & 7) * 8;
        const uint32_t so = (uint32_t)(r * AQS + c) * 2;
        const size_t g = gbase + (size_t)r * DIMN + c;
        cp16(smem_u32(Qs) + so, q16 + g);
        cp16(smem_u32(Ks) + so, k16 + g);
        cp16(smem_u32(Vs) + so, v16 + g);
    }
    {
        const int r = tid >> 3, c = (tid & 7) * 8;
        const size_t g = ((size_t)(b * NLEN + r * BLKLEN)) * DIMN + h * DK + c;
        const uint32_t so = (uint32_t)(r * AQS + c) * 2;
        cp16(smem_u32(gk) + so, k16 + g);
        cp16(smem_u32(gv) + so, v16 + g);
    }
    cp_commit();
    cpwait<0>();
    __syncthreads();

    const float scale = 0.125f;

    // warp 0: global attention for this block's first token
    if (wid == 0) {
        float s = 0.f;
#pragma unroll
        for (int i = 0; i < DK / 2; i++) {
            float2 qf = __half22float2(*(const __half2*)&Qs[2 * i]);
            float2 kf = __half22float2(*(const __half2*)&gk[lane * AQS + 2 * i]);
            s += qf.x * kf.x + qf.y * kf.y;
        }
        float p = __expf(s * scale);
        float lsum = p;
#pragma unroll
        for (int d = 1; d < 32; d <<= 1)
            lsum += __shfl_xor_sync(0xFFFFFFFFu, lsum, d);
        gp[lane] = p;
        __syncwarp();
        const float inv = 1.0f / lsum;
        float o0 = 0.f, o1 = 0.f;
#pragma unroll
        for (int k = 0; k < NB; k++) {
            const float pk = gp[k];
            float2 vf = __half22float2(*(const __half2*)&gv[k * AQS + 2 * lane]);
            o0 += pk * vf.x; o1 += pk * vf.y;
        }
        gout[2 * lane]     = o0 * inv;
        gout[2 * lane + 1] = o1 * inv;
        __syncwarp();
    }

    const int cbase = (lane & 3) * 2;
    const int gr = lane >> 2;
    const uint32_t loff = (uint32_t)((lane & 15) * AQS + (lane >> 4) * 8) * 2;
    const int vmat = lane >> 3;
    const uint32_t vb = smem_u32(Vs) +
        (uint32_t)(((vmat & 1) * 8 + (lane & 7)) * AQS + (vmat >> 1) * 8) * 2;

    const int niter = (wid == 7) ? 2 : 1;
    for (int it = 0; it < niter; it++) {
        const int t = (it == 0) ? wid : 8;
        const int m0 = t * 16;

        uint32_t aq[4][4];
        {
            const uint32_t qb = smem_u32(Qs) + (uint32_t)(m0 * AQS) * 2 + loff;
#pragma unroll
            for (int ks = 0; ks < 4; ks++) ldm_x4(aq[ks], qb + ks * 32);
        }

        uint32_t P2[17][2];
        float l0 = 0.f, l1 = 0.f;
        const uint32_t kb = smem_u32(Ks) + loff;
#pragma unroll
        for (int jp = 0; jp < 8; jp++) {
            float e0[4] = {0.f, 0.f, 0.f, 0.f};
            float e1[4] = {0.f, 0.f, 0.f, 0.f};
            const uint32_t kjb = kb + (uint32_t)(jp * 16 * AQS) * 2;
#pragma unroll
            for (int ks = 0; ks < 4; ks++) {
                uint32_t r[4];
                ldm_x4(r, kjb + ks * 32);
                mma_h(e0, aq[ks], r[0], r[2]);
                mma_h(e1, aq[ks], r[1], r[3]);
            }
            float p00 = __expf(e0[0] * scale), p01 = __expf(e0[1] * scale);
            float p02 = __expf(e0[2] * scale), p03 = __expf(e0[3] * scale);
            float p10 = __expf(e1[0] * scale), p11 = __expf(e1[1] * scale);
            float p12 = __expf(e1[2] * scale), p13 = __expf(e1[3] * scale);
            l0 += (p00 + p01) + (p10 + p11);
            l1 += (p02 + p03) + (p12 + p13);
            P2[2 * jp][0] = packh2(p00, p01);
            P2[2 * jp][1] = packh2(p02, p03);
            P2[2 * jp + 1][0] = packh2(p10, p11);
            P2[2 * jp + 1][1] = packh2(p12, p13);
        }
        {
            float e0[4] = {0.f, 0.f, 0.f, 0.f};
            const uint32_t kjb = kb + (uint32_t)(128 * AQS) * 2;
#pragma unroll
            for (int ks = 0; ks < 4; ks++) {
                uint32_t r[4];
                ldm_x4(r, kjb + ks * 32);
                mma_h(e0, aq[ks], r[0], r[2]);
            }
            const bool v = (cbase == 0);
            float p0 = v ? __expf(e0[0] * scale) : 0.f;
            float p2 = v ? __expf(e0[2] * scale) : 0.f;
            l0 += p0; l1 += p2;
            P2[16][0] = packh2(p0, 0.f);
            P2[16][1] = packh2(p2, 0.f);
        }
        l0 += __shfl_xor_sync(0xFFFFFFFFu, l0, 1);
        l0 += __shfl_xor_sync(0xFFFFFFFFu, l0, 2);
        l1 += __shfl_xor_sync(0xFFFFFFFFu, l1, 1);
        l1 += __shfl_xor_sync(0xFFFFFFFFu, l1, 2);

        float oacc[8][4];
#pragma unroll
        for (int g = 0; g < 8; g++)
#pragma unroll
            for (int u = 0; u < 4; u++) oacc[g][u] = 0.f;

#pragma unroll
        for (int kp = 0; kp < 9; kp++) {
            uint32_t pa[4];
            pa[0] = P2[2 * kp][0];
            pa[1] = P2[2 * kp][1];
            if (kp < 8) { pa[2] = P2[2 * kp + 1][0]; pa[3] = P2[2 * kp + 1][1]; }
            else        { pa[2] = 0u; pa[3] = 0u; }
            const uint32_t vkb = vb + (uint32_t)(kp * 16 * AQS) * 2;
#pragma unroll
            for (int g = 0; g < 4; g++) {
                uint32_t r[4];
                ldm_x4_t(r, vkb + g * 32);
                mma_h(oacc[2 * g],     pa, r[0], r[1]);
                mma_h(oacc[2 * g + 1], pa, r[2], r[3]);
            }
        }

        const float rl0 = 1.0f / l0, rl1 = 1.0f / l1;
        const int r0 = m0 + gr, r1 = r0 + 8;
#pragma unroll
        for (int g = 0; g < 8; g++) {
            const int col = g * 8 + cbase;
            float o0 = oacc[g][0] * rl0, o1 = oacc[g][1] * rl0;
            float o2 = oacc[g][2] * rl1, o3 = oacc[g][3] * rl1;
            if (r0 == 0) { o0 += gout[col]; o1 += gout[col + 1]; }
            if (r0 < BLKLEN)
                *(__half2*)(a16 + gbase + (size_t)r0 * DIMN + col) =
                    __floats2half2_rn(o0, o1);
            if (r1 < BLKLEN)
                *(__half2*)(a16 + gbase + (size_t)r1 * DIMN + col) =
                    __floats2half2_rn(o2, o3);
        }
    }
}

// ---------------------------------------------------------------------------
extern "C" void kernel_launch(void* const* d_in, const int* in_sizes, int n_in,
                              void* d_out, int out_size)
{
    const float* x  = (const float*)d_in[0];
    const float* Wq = (const float*)d_in[1];
    const float* Wk = (const float*)d_in[2];
    const float* Wv = (const float*)d_in[3];
    const float* Wo = (const float*)d_in[4];
    const float* bo = (const float*)d_in[5];
    float* out = (float*)d_out;

    __half *x16, *q16, *k16, *v16, *a16, *w16;
    cudaGetSymbolAddress((void**)&x16, g_x16);
    cudaGetSymbolAddress((void**)&q16, g_q16);
    cudaGetSymbolAddress((void**)&k16, g_k16);
    cudaGetSymbolAddress((void**)&v16, g_v16);
    cudaGetSymbolAddress((void**)&a16, g_a16);
    cudaGetSymbolAddress((void**)&w16, g_w16);

    cudaFuncSetAttribute(gemm_qkv, cudaFuncAttributeMaxDynamicSharedMemorySize, GEMM_SMEM);
    cudaFuncSetAttribute(gemm_out, cudaFuncAttributeMaxDynamicSharedMemorySize, GEMM_SMEM);
    cudaFuncSetAttribute(blk_attn_tc, cudaFuncAttributeMaxDynamicSharedMemorySize, AT_SMEM);

    const int W = DIMN * DIMN;
    const int n4x = TOK * DIMN / 4;
    const int n4w = W / 4;

    cvt_h4<<<(n4x + 255) / 256, 256>>>((const float4*)x, (__half2*)x16, n4x);
    dim3 gW((n4w + 255) / 256, 4);
    cvt_w4<<<gW, 256>>>((const float4*)Wq, (const float4*)Wk,
                        (const float4*)Wv, (const float4*)Wo,
                        (__half2*)w16, n4w);

    dim3 gQKV(DIMN / 128, TOK / 128, 3);   // (8, 129, 3)
    gemm_qkv<<<gQKV, 256, GEMM_SMEM>>>(x16,
        w16 + 0 * W, w16 + 1 * W, w16 + 2 * W, q16, k16, v16);

    blk_attn_tc<<<B_SZ * NB * HEADS, 256, AT_SMEM>>>(q16, k16, v16, a16);

    dim3 gO(DIMN / 128, TOK / 128);        // (8, 129)
    gemm_out<<<gO, 256, GEMM_SMEM>>>(a16, w16 + 3 * W, bo, out);
}

// round 16
// speedup vs baseline: 1.2575x; 1.1017x over previous
#include <cuda_runtime.h>
#include <cuda_fp16.h>
#include <cstdint>
#include <math.h>

#define B_SZ   4
#define NLEN   4128
#define DIMN   1024
#define HEADS  16
#define BLKLEN 129
#define NB     32
#define DK     64
#define TOK    (B_SZ * NLEN)   // 16512

// ---------------- scratch (device globals: allocation-free) ----------------
__device__ __half g_x16[TOK * DIMN];
__device__ __half g_q16[TOK * DIMN];
__device__ __half g_k16[TOK * DIMN];
__device__ __half g_v16[TOK * DIMN];
__device__ __half g_a16[TOK * DIMN];
__device__ __half g_w16[4 * DIMN * DIMN];

// ============================ helpers ======================================
__device__ __forceinline__ uint32_t smem_u32(const void* p) {
    return (uint32_t)__cvta_generic_to_shared(p);
}
__device__ __forceinline__ void cp16(uint32_t d, const void* s) {
    asm volatile("cp.async.cg.shared.global [%0], [%1], 16;\n" :: "r"(d), "l"(s));
}
__device__ __forceinline__ void cp_commit() {
    asm volatile("cp.async.commit_group;\n");
}
template<int N_> __device__ __forceinline__ void cpwait() {
    asm volatile("cp.async.wait_group %0;\n" :: "n"(N_));
}
__device__ __forceinline__ void ldm_x4(uint32_t* r, uint32_t a) {
    asm volatile("ldmatrix.sync.aligned.m8n8.x4.shared.b16 {%0,%1,%2,%3}, [%4];\n"
                 : "=r"(r[0]), "=r"(r[1]), "=r"(r[2]), "=r"(r[3]) : "r"(a));
}
__device__ __forceinline__ void ldm_x4_t(uint32_t* r, uint32_t a) {
    asm volatile("ldmatrix.sync.aligned.m8n8.x4.trans.shared.b16 {%0,%1,%2,%3}, [%4];\n"
                 : "=r"(r[0]), "=r"(r[1]), "=r"(r[2]), "=r"(r[3]) : "r"(a));
}
__device__ __forceinline__ void mma_h(float* d, const uint32_t* a,
                                      uint32_t b0, uint32_t b1) {
    asm volatile("mma.sync.aligned.m16n8k16.row.col.f32.f16.f16.f32 "
                 "{%0,%1,%2,%3}, {%4,%5,%6,%7}, {%8,%9}, {%0,%1,%2,%3};\n"
                 : "+f"(d[0]), "+f"(d[1]), "+f"(d[2]), "+f"(d[3])
                 : "r"(a[0]), "r"(a[1]), "r"(a[2]), "r"(a[3]), "r"(b0), "r"(b1));
}
__device__ __forceinline__ uint32_t packh2(float x, float y) {
    __half2 h = __floats2half2_rn(x, y);
    return *(uint32_t*)&h;
}

// ---------------------------------------------------------------------------
// conversions: 4 x float4 per thread (MLP=4), uint4 stores
// ---------------------------------------------------------------------------
__global__ void cvt_h16(const float4* __restrict__ in, uint4* __restrict__ out,
                        int n16)
{
    int i = blockIdx.x * blockDim.x + threadIdx.x;   // one per 16 floats
    if (i >= n16) return;
    float4 a = in[4 * i + 0];
    float4 b = in[4 * i + 1];
    float4 c = in[4 * i + 2];
    float4 d = in[4 * i + 3];
    uint4 o0, o1;
    o0.x = packh2(a.x, a.y); o0.y = packh2(a.z, a.w);
    o0.z = packh2(b.x, b.y); o0.w = packh2(b.z, b.w);
    o1.x = packh2(c.x, c.y); o1.y = packh2(c.z, c.w);
    o1.z = packh2(d.x, d.y); o1.w = packh2(d.z, d.w);
    out[2 * i + 0] = o0;
    out[2 * i + 1] = o1;
}

__global__ void cvt_w16(const float4* __restrict__ W0, const float4* __restrict__ W1,
                        const float4* __restrict__ W2, const float4* __restrict__ W3,
                        uint4* __restrict__ out, int n16)
{
    const int z = blockIdx.y;
    const float4* src = (z == 0) ? W0 : (z == 1) ? W1 : (z == 2) ? W2 : W3;
    uint4* dst = out + (size_t)z * (DIMN * DIMN / 8);
    int i = blockIdx.x * blockDim.x + threadIdx.x;
    if (i >= n16) return;
    float4 a = src[4 * i + 0];
    float4 b = src[4 * i + 1];
    float4 c = src[4 * i + 2];
    float4 d = src[4 * i + 3];
    uint4 o0, o1;
    o0.x = packh2(a.x, a.y); o0.y = packh2(a.z, a.w);
    o0.z = packh2(b.x, b.y); o0.w = packh2(b.z, b.w);
    o1.x = packh2(c.x, c.y); o1.y = packh2(c.z, c.w);
    o1.z = packh2(d.x, d.y); o1.w = packh2(d.z, d.w);
    dst[2 * i + 0] = o0;
    dst[2 * i + 1] = o1;
}

// ---------------------------------------------------------------------------
// Single-term fp16 HMMA GEMM core: C[M,N] = A[M,K] @ B[N,K]^T
// BM=BN=128, BK=32, 3-stage cp.async, 8 warps, 2 CTAs/SM.  (proven R7)
// ---------------------------------------------------------------------------
#define SSTRIDE 40
#define TILE_B (128 * SSTRIDE * 2)   // 10240 B
#define STAGE_B (2 * TILE_B)         // 20480 B
#define GEMM_SMEM (3 * STAGE_B)      // 61440 B
#define KT32 (DIMN / 32)             // 32

__device__ __forceinline__ void gemm_core(
    const __half* pA, const __half* pB,
    uint32_t dst0, uint32_t aoff, uint32_t boff,
    float acc[2][8][4])
{
#define PREF(kt, st) do {                                                   \
        uint32_t db = dst0 + (uint32_t)(st) * STAGE_B;                      \
        const __half* s0 = pA + (kt) * 32;                                  \
        const __half* s1 = pB + (kt) * 32;                                  \
        cp16(db,          s0); cp16(db + 16,          s0 + 8);              \
        cp16(db + TILE_B, s1); cp16(db + TILE_B + 16, s1 + 8);              \
        cp_commit();                                                        \
    } while (0)

    PREF(0, 0);
    PREF(1, 1);
    for (int kt = 0; kt < KT32; kt++) {
        const int st = kt % 3;
        if (kt + 2 < KT32)      { PREF(kt + 2, (kt + 2) % 3); cpwait<2>(); }
        else if (kt + 1 < KT32) { cpwait<1>(); }
        else                    { cpwait<0>(); }
        __syncthreads();

        const uint32_t sb = (uint32_t)st * STAGE_B;
#pragma unroll
        for (int kk = 0; kk < 2; kk++) {
            const uint32_t ko = sb + kk * 32;
            uint32_t a[2][4], b[8][2];
            ldm_x4(a[0], aoff + ko);
            ldm_x4(a[1], aoff + ko + 16 * SSTRIDE * 2);
#pragma unroll
            for (int ng = 0; ng < 4; ng++) {
                uint32_t r[4];
                ldm_x4(r, boff + ko + ng * 16 * SSTRIDE * 2);
                b[2 * ng][0] = r[0]; b[2 * ng][1] = r[2];
                b[2 * ng + 1][0] = r[1]; b[2 * ng + 1][1] = r[3];
            }
#pragma unroll
            for (int mt = 0; mt < 2; mt++)
#pragma unroll
                for (int nt = 0; nt < 8; nt++)
                    mma_h(acc[mt][nt], a[mt], b[nt][0], b[nt][1]);
        }
        __syncthreads();
    }
#undef PREF
}

// fused QKV: z selects weight + fp16 output
__global__ __launch_bounds__(256, 2)
void gemm_qkv(const __half* __restrict__ A,
              const __half* __restrict__ W0, const __half* __restrict__ W1,
              const __half* __restrict__ W2,
              __half* __restrict__ O0, __half* __restrict__ O1,
              __half* __restrict__ O2)
{
    extern __shared__ __half smemh[];
    const uint32_t smem = smem_u32(smemh);
    const int tid = threadIdx.x, lane = tid & 31, w = tid >> 5;
    const int m0 = blockIdx.y * 128, n0 = blockIdx.x * 128;
    const __half* Bm = (blockIdx.z == 0) ? W0 : (blockIdx.z == 1 ? W1 : W2);
    __half* C = (blockIdx.z == 0) ? O0 : (blockIdx.z == 1 ? O1 : O2);

    const int lr = tid & 127, lc = (tid >> 7) * 16;
    const __half* pA = A  + (size_t)(m0 + lr) * DIMN + lc;
    const __half* pB = Bm + (size_t)(n0 + lr) * DIMN + lc;
    const uint32_t dst0 = smem + (uint32_t)(lr * SSTRIDE + lc) * 2;

    const int wm = w & 3, wn = w >> 2;
    const uint32_t aoff = smem +
        (uint32_t)((wm * 32 + (lane & 15)) * SSTRIDE + (lane >> 4) * 8) * 2;
    const uint32_t boff = smem + TILE_B +
        (uint32_t)((wn * 64 + (lane & 15)) * SSTRIDE + (lane >> 4) * 8) * 2;

    float acc[2][8][4];
#pragma unroll
    for (int i = 0; i < 2; i++)
#pragma unroll
        for (int j = 0; j < 8; j++)
#pragma unroll
            for (int t = 0; t < 4; t++) acc[i][j][t] = 0.f;

    gemm_core(pA, pB, dst0, aoff, boff, acc);

    const int gr = lane >> 2, gc = (lane & 3) * 2;
#pragma unroll
    for (int mt = 0; mt < 2; mt++) {
        const int row = m0 + wm * 32 + mt * 16 + gr;
#pragma unroll
        for (int nt = 0; nt < 8; nt++) {
            const int col = n0 + wn * 64 + nt * 8 + gc;
            *(__half2*)(C + (size_t)row * DIMN + col) =
                __floats2half2_rn(acc[mt][nt][0], acc[mt][nt][1]);
            *(__half2*)(C + (size_t)(row + 8) * DIMN + col) =
                __floats2half2_rn(acc[mt][nt][2], acc[mt][nt][3]);
        }
    }
}

// final GEMM: fp32 out + bias
__global__ __launch_bounds__(256, 2)
void gemm_out(const __half* __restrict__ A, const __half* __restrict__ Bm,
              const float* __restrict__ bias, float* __restrict__ C)
{
    extern __shared__ __half smemh[];
    const uint32_t smem = smem_u32(smemh);
    const int tid = threadIdx.x, lane = tid & 31, w = tid >> 5;
    const int m0 = blockIdx.y * 128, n0 = blockIdx.x * 128;

    const int lr = tid & 127, lc = (tid >> 7) * 16;
    const __half* pA = A  + (size_t)(m0 + lr) * DIMN + lc;
    const __half* pB = Bm + (size_t)(n0 + lr) * DIMN + lc;
    const uint32_t dst0 = smem + (uint32_t)(lr * SSTRIDE + lc) * 2;

    const int wm = w & 3, wn = w >> 2;
    const uint32_t aoff = smem +
        (uint32_t)((wm * 32 + (lane & 15)) * SSTRIDE + (lane >> 4) * 8) * 2;
    const uint32_t boff = smem + TILE_B +
        (uint32_t)((wn * 64 + (lane & 15)) * SSTRIDE + (lane >> 4) * 8) * 2;

    float acc[2][8][4];
#pragma unroll
    for (int i = 0; i < 2; i++)
#pragma unroll
        for (int j = 0; j < 8; j++)
#pragma unroll
            for (int t = 0; t < 4; t++) acc[i][j][t] = 0.f;

    gemm_core(pA, pB, dst0, aoff, boff, acc);

    const int gr = lane >> 2, gc = (lane & 3) * 2;
#pragma unroll
    for (int mt = 0; mt < 2; mt++) {
        const int row = m0 + wm * 32 + mt * 16 + gr;
#pragma unroll
        for (int nt = 0; nt < 8; nt++) {
            const int col = n0 + wn * 64 + nt * 8 + gc;
            const float b0 = bias[col], b1 = bias[col + 1];
            *(float2*)(C + (size_t)row * DIMN + col) =
                make_float2(acc[mt][nt][0] + b0, acc[mt][nt][1] + b1);
            *(float2*)(C + (size_t)(row + 8) * DIMN + col) =
                make_float2(acc[mt][nt][2] + b0, acc[mt][nt][3] + b1);
        }
    }
}

// ---------------------------------------------------------------------------
// HMMA block-local attention + fused global attention (proven R7 version).
// One CTA per (b, blk, head), 8 warps x 16 query rows (warp 7 takes tile 8).
// ---------------------------------------------------------------------------
#define AQS 72                               // smem row stride (halfs)
#define HQ  (144 * AQS)                      // halfs per tile
#define GK_OFF (3 * HQ)
#define GV_OFF (GK_OFF + 32 * AQS)
#define GP_BYTE ((GV_OFF + 32 * AQS) * 2)
#define GOUT_BYTE (GP_BYTE + 32 * 4)
#define AT_SMEM (GOUT_BYTE + 64 * 4)         // 71808 B

__global__ __launch_bounds__(256, 2)
void blk_attn_tc(const __half* __restrict__ q16, const __half* __restrict__ k16,
                 const __half* __restrict__ v16, __half* __restrict__ a16)
{
    extern __shared__ __half sh[];
    __half* Qs = sh;
    __half* Ks = sh + HQ;
    __half* Vs = sh + 2 * HQ;
    __half* gk = sh + GK_OFF;
    __half* gv = sh + GV_OFF;
    float* gp   = (float*)((char*)sh + GP_BYTE);
    float* gout = (float*)((char*)sh + GOUT_BYTE);

    const int bid = blockIdx.x;
    const int h = bid & 15, blk = (bid >> 4) & 31, b = bid >> 9;
    const size_t gbase = ((size_t)(b * NLEN + blk * BLKLEN)) * DIMN + h * DK;
    const int tid = threadIdx.x, lane = tid & 31, wid = tid >> 5;

    const uint4 z4 = make_uint4(0, 0, 0, 0);
    for (int i = tid; i < 360; i += 256) {
        const int t = i / 120, j = i % 120;
        const int r = 129 + (j >> 3), c = (j & 7) * 8;
        __half* base = (t == 0) ? Qs : (t == 1) ? Ks : Vs;
        *(uint4*)&base[r * AQS + c] = z4;
    }
    for (int i = tid; i < 1032; i += 256) {
        const int r = i >> 3, c = (i & 7) * 8;
        const uint32_t so = (uint32_t)(r * AQS + c) * 2;
        const size_t g = gbase + (size_t)r * DIMN + c;
        cp16(smem_u32(Qs) + so, q16 + g);
        cp16(smem_u32(Ks) + so, k16 + g);
        cp16(smem_u32(Vs) + so, v16 + g);
    }
    {
        const int r = tid >> 3, c = (tid & 7) * 8;
        const size_t g = ((size_t)(b * NLEN + r * BLKLEN)) * DIMN + h * DK + c;
        const uint32_t so = (uint32_t)(r * AQS + c) * 2;
        cp16(smem_u32(gk) + so, k16 + g);
        cp16(smem_u32(gv) + so, v16 + g);
    }
    cp_commit();
    cpwait<0>();
    __syncthreads();

    const float scale = 0.125f;

    // warp 0: global attention for this block's first token
    if (wid == 0) {
        float s = 0.f;
#pragma unroll
        for (int i = 0; i < DK / 2; i++) {
            float2 qf = __half22float2(*(const __half2*)&Qs[2 * i]);
            float2 kf = __half22float2(*(const __half2*)&gk[lane * AQS + 2 * i]);
            s += qf.x * kf.x + qf.y * kf.y;
        }
        float p = __expf(s * scale);
        float lsum = p;
#pragma unroll
        for (int d = 1; d < 32; d <<= 1)
            lsum += __shfl_xor_sync(0xFFFFFFFFu, lsum, d);
        gp[lane] = p;
        __syncwarp();
        const float inv = 1.0f / lsum;
        float o0 = 0.f, o1 = 0.f;
#pragma unroll
        for (int k = 0; k < NB; k++) {
            const float pk = gp[k];
            float2 vf = __half22float2(*(const __half2*)&gv[k * AQS + 2 * lane]);
            o0 += pk * vf.x; o1 += pk * vf.y;
        }
        gout[2 * lane]     = o0 * inv;
        gout[2 * lane + 1] = o1 * inv;
        __syncwarp();
    }

    const int cbase = (lane & 3) * 2;
    const int gr = lane >> 2;
    const uint32_t loff = (uint32_t)((lane & 15) * AQS + (lane >> 4) * 8) * 2;
    const int vmat = lane >> 3;
    const uint32_t vb = smem_u32(Vs) +
        (uint32_t)(((vmat & 1) * 8 + (lane & 7)) * AQS + (vmat >> 1) * 8) * 2;

    const int niter = (wid == 7) ? 2 : 1;
    for (int it = 0; it < niter; it++) {
        const int t = (it == 0) ? wid : 8;
        const int m0 = t * 16;

        uint32_t aq[4][4];
        {
            const uint32_t qb = smem_u32(Qs) + (uint32_t)(m0 * AQS) * 2 + loff;
#pragma unroll
            for (int ks = 0; ks < 4; ks++) ldm_x4(aq[ks], qb + ks * 32);
        }

        uint32_t P2[17][2];
        float l0 = 0.f, l1 = 0.f;
        const uint32_t kb = smem_u32(Ks) + loff;
#pragma unroll
        for (int jp = 0; jp < 8; jp++) {
            float e0[4] = {0.f, 0.f, 0.f, 0.f};
            float e1[4] = {0.f, 0.f, 0.f, 0.f};
            const uint32_t kjb = kb + (uint32_t)(jp * 16 * AQS) * 2;
#pragma unroll
            for (int ks = 0; ks < 4; ks++) {
                uint32_t r[4];
                ldm_x4(r, kjb + ks * 32);
                mma_h(e0, aq[ks], r[0], r[2]);
                mma_h(e1, aq[ks], r[1], r[3]);
            }
            float p00 = __expf(e0[0] * scale), p01 = __expf(e0[1] * scale);
            float p02 = __expf(e0[2] * scale), p03 = __expf(e0[3] * scale);
            float p10 = __expf(e1[0] * scale), p11 = __expf(e1[1] * scale);
            float p12 = __expf(e1[2] * scale), p13 = __expf(e1[3] * scale);
            l0 += (p00 + p01) + (p10 + p11);
            l1 += (p02 + p03) + (p12 + p13);
            P2[2 * jp][0] = packh2(p00, p01);
            P2[2 * jp][1] = packh2(p02, p03);
            P2[2 * jp + 1][0] = packh2(p10, p11);
            P2[2 * jp + 1][1] = packh2(p12, p13);
        }
        {
            float e0[4] = {0.f, 0.f, 0.f, 0.f};
            const uint32_t kjb = kb + (uint32_t)(128 * AQS) * 2;
#pragma unroll
            for (int ks = 0; ks < 4; ks++) {
                uint32_t r[4];
                ldm_x4(r, kjb + ks * 32);
                mma_h(e0, aq[ks], r[0], r[2]);
            }
            const bool v = (cbase == 0);
            float p0 = v ? __expf(e0[0] * scale) : 0.f;
            float p2 = v ? __expf(e0[2] * scale) : 0.f;
            l0 += p0; l1 += p2;
            P2[16][0] = packh2(p0, 0.f);
            P2[16][1] = packh2(p2, 0.f);
        }
        l0 += __shfl_xor_sync(0xFFFFFFFFu, l0, 1);
        l0 += __shfl_xor_sync(0xFFFFFFFFu, l0, 2);
        l1 += __shfl_xor_sync(0xFFFFFFFFu, l1, 1);
        l1 += __shfl_xor_sync(0xFFFFFFFFu, l1, 2);

        float oacc[8][4];
#pragma unroll
        for (int g = 0; g < 8; g++)
#pragma unroll
            for (int u = 0; u < 4; u++) oacc[g][u] = 0.f;

#pragma unroll
        for (int kp = 0; kp < 9; kp++) {
            uint32_t pa[4];
            pa[0] = P2[2 * kp][0];
            pa[1] = P2[2 * kp][1];
            if (kp < 8) { pa[2] = P2[2 * kp + 1][0]; pa[3] = P2[2 * kp + 1][1]; }
            else        { pa[2] = 0u; pa[3] = 0u; }
            const uint32_t vkb = vb + (uint32_t)(kp * 16 * AQS) * 2;
#pragma unroll
            for (int g = 0; g < 4; g++) {
                uint32_t r[4];
                ldm_x4_t(r, vkb + g * 32);
                mma_h(oacc[2 * g],     pa, r[0], r[1]);
                mma_h(oacc[2 * g + 1], pa, r[2], r[3]);
            }
        }

        const float rl0 = 1.0f / l0, rl1 = 1.0f / l1;
        const int r0 = m0 + gr, r1 = r0 + 8;
#pragma unroll
        for (int g = 0; g < 8; g++) {
            const int col = g * 8 + cbase;
            float o0 = oacc[g][0] * rl0, o1 = oacc[g][1] * rl0;
            float o2 = oacc[g][2] * rl1, o3 = oacc[g][3] * rl1;
            if (r0 == 0) { o0 += gout[col]; o1 += gout[col + 1]; }
            if (r0 < BLKLEN)
                *(__half2*)(a16 + gbase + (size_t)r0 * DIMN + col) =
                    __floats2half2_rn(o0, o1);
            if (r1 < BLKLEN)
                *(__half2*)(a16 + gbase + (size_t)r1 * DIMN + col) =
                    __floats2half2_rn(o2, o3);
        }
    }
}

// ---------------------------------------------------------------------------
extern "C" void kernel_launch(void* const* d_in, const int* in_sizes, int n_in,
                              void* d_out, int out_size)
{
    const float* x  = (const float*)d_in[0];
    const float* Wq = (const float*)d_in[1];
    const float* Wk = (const float*)d_in[2];
    const float* Wv = (const float*)d_in[3];
    const float* Wo = (const float*)d_in[4];
    const float* bo = (const float*)d_in[5];
    float* out = (float*)d_out;

    __half *x16, *q16, *k16, *v16, *a16, *w16;
    cudaGetSymbolAddress((void**)&x16, g_x16);
    cudaGetSymbolAddress((void**)&q16, g_q16);
    cudaGetSymbolAddress((void**)&k16, g_k16);
    cudaGetSymbolAddress((void**)&v16, g_v16);
    cudaGetSymbolAddress((void**)&a16, g_a16);
    cudaGetSymbolAddress((void**)&w16, g_w16);

    cudaFuncSetAttribute(gemm_qkv, cudaFuncAttributeMaxDynamicSharedMemorySize, GEMM_SMEM);
    cudaFuncSetAttribute(gemm_out, cudaFuncAttributeMaxDynamicSharedMemorySize, GEMM_SMEM);
    cudaFuncSetAttribute(blk_attn_tc, cudaFuncAttributeMaxDynamicSharedMemorySize, AT_SMEM);

    const int W = DIMN * DIMN;
    const int n16x = TOK * DIMN / 16;       // 1,056,768
    const int n16w = W / 16;                // 65,536

    cvt_h16<<<(n16x + 255) / 256, 256>>>((const float4*)x, (uint4*)x16, n16x);
    dim3 gW((n16w + 255) / 256, 4);
    cvt_w16<<<gW, 256>>>((const float4*)Wq, (const float4*)Wk,
                         (const float4*)Wv, (const float4*)Wo,
                         (uint4*)w16, n16w);

    dim3 gQKV(DIMN / 128, TOK / 128, 3);   // (8, 129, 3)
    gemm_qkv<<<gQKV, 256, GEMM_SMEM>>>(x16,
        w16 + 0 * W, w16 + 1 * W, w16 + 2 * W, q16, k16, v16);

    blk_attn_tc<<<B_SZ * NB * HEADS, 256, AT_SMEM>>>(q16, k16, v16, a16);

    dim3 gO(DIMN / 128, TOK / 128);        // (8, 129)
    gemm_out<<<gO, 256, GEMM_SMEM>>>(a16, w16 + 3 * W, bo, out);
}

// round 17
// speedup vs baseline: 1.5772x; 1.2543x over previous
#include <cuda_runtime.h>
#include <cuda_fp16.h>
#include <cstdint>
#include <math.h>

#define B_SZ   4
#define NLEN   4128
#define DIMN   1024
#define HEADS  16
#define BLKLEN 129
#define NB     32
#define DK     64
#define TOK    (B_SZ * NLEN)   // 16512

// ---------------- scratch (device globals: allocation-free) ----------------
__device__ __half g_x16[TOK * DIMN];
__device__ __half g_q16[TOK * DIMN];
__device__ __half g_k16[TOK * DIMN];
__device__ __half g_v16[TOK * DIMN];
__device__ __half g_a16[TOK * DIMN];
__device__ __half g_w16[4 * DIMN * DIMN];

// ============================ helpers ======================================
__device__ __forceinline__ uint32_t smem_u32(const void* p) {
    return (uint32_t)__cvta_generic_to_shared(p);
}
__device__ __forceinline__ void cp16(uint32_t d, const void* s) {
    asm volatile("cp.async.cg.shared.global [%0], [%1], 16;\n" :: "r"(d), "l"(s));
}
__device__ __forceinline__ void cp_commit() {
    asm volatile("cp.async.commit_group;\n");
}
template<int N_> __device__ __forceinline__ void cpwait() {
    asm volatile("cp.async.wait_group %0;\n" :: "n"(N_));
}
__device__ __forceinline__ void ldm_x4(uint32_t* r, uint32_t a) {
    asm volatile("ldmatrix.sync.aligned.m8n8.x4.shared.b16 {%0,%1,%2,%3}, [%4];\n"
                 : "=r"(r[0]), "=r"(r[1]), "=r"(r[2]), "=r"(r[3]) : "r"(a));
}
__device__ __forceinline__ void ldm_x4_t(uint32_t* r, uint32_t a) {
    asm volatile("ldmatrix.sync.aligned.m8n8.x4.trans.shared.b16 {%0,%1,%2,%3}, [%4];\n"
                 : "=r"(r[0]), "=r"(r[1]), "=r"(r[2]), "=r"(r[3]) : "r"(a));
}
__device__ __forceinline__ void mma_h(float* d, const uint32_t* a,
                                      uint32_t b0, uint32_t b1) {
    asm volatile("mma.sync.aligned.m16n8k16.row.col.f32.f16.f16.f32 "
                 "{%0,%1,%2,%3}, {%4,%5,%6,%7}, {%8,%9}, {%0,%1,%2,%3};\n"
                 : "+f"(d[0]), "+f"(d[1]), "+f"(d[2]), "+f"(d[3])
                 : "r"(a[0]), "r"(a[1]), "r"(a[2]), "r"(a[3]), "r"(b0), "r"(b1));
}
__device__ __forceinline__ uint32_t packh2(float x, float y) {
    __half2 h = __floats2half2_rn(x, y);
    return *(uint32_t*)&h;
}

// ---------------------------------------------------------------------------
// conversions: 4 x float4 per thread (MLP=4), uint4 stores
// ---------------------------------------------------------------------------
__global__ void cvt_h16(const float4* __restrict__ in, uint4* __restrict__ out,
                        int n16)
{
    int i = blockIdx.x * blockDim.x + threadIdx.x;
    if (i >= n16) return;
    float4 a = in[4 * i + 0];
    float4 b = in[4 * i + 1];
    float4 c = in[4 * i + 2];
    float4 d = in[4 * i + 3];
    uint4 o0, o1;
    o0.x = packh2(a.x, a.y); o0.y = packh2(a.z, a.w);
    o0.z = packh2(b.x, b.y); o0.w = packh2(b.z, b.w);
    o1.x = packh2(c.x, c.y); o1.y = packh2(c.z, c.w);
    o1.z = packh2(d.x, d.y); o1.w = packh2(d.z, d.w);
    out[2 * i + 0] = o0;
    out[2 * i + 1] = o1;
}

__global__ void cvt_w16(const float4* __restrict__ W0, const float4* __restrict__ W1,
                        const float4* __restrict__ W2, const float4* __restrict__ W3,
                        uint4* __restrict__ out, int n16)
{
    const int z = blockIdx.y;
    const float4* src = (z == 0) ? W0 : (z == 1) ? W1 : (z == 2) ? W2 : W3;
    uint4* dst = out + (size_t)z * (DIMN * DIMN / 8);
    int i = blockIdx.x * blockDim.x + threadIdx.x;
    if (i >= n16) return;
    float4 a = src[4 * i + 0];
    float4 b = src[4 * i + 1];
    float4 c = src[4 * i + 2];
    float4 d = src[4 * i + 3];
    uint4 o0, o1;
    o0.x = packh2(a.x, a.y); o0.y = packh2(a.z, a.w);
    o0.z = packh2(b.x, b.y); o0.w = packh2(b.z, b.w);
    o1.x = packh2(c.x, c.y); o1.y = packh2(c.z, c.w);
    o1.z = packh2(d.x, d.y); o1.w = packh2(d.z, d.w);
    dst[2 * i + 0] = o0;
    dst[2 * i + 1] = o1;
}

// ---------------------------------------------------------------------------
// Single-term fp16 HMMA GEMM: C[M,N] = A[M,K] @ B[N,K]^T
// BM=BN=128, BK=32, 3-stage cp.async, 512 threads (16 warps, 4m x 4n,
// warptile 32x32), 1 CTA/SM. Halves per-SM L2 traffic vs 2x256 config.
// ---------------------------------------------------------------------------
#define SSTRIDE 40
#define TILE_B (128 * SSTRIDE * 2)   // 10240 B
#define STAGE_B (2 * TILE_B)         // 20480 B
#define GEMM_SMEM (3 * STAGE_B)      // 61440 B
#define KT32 (DIMN / 32)             // 32

__device__ __forceinline__ void gemm_core(
    const __half* pA, const __half* pB,
    uint32_t dst0, uint32_t aoff, uint32_t boff,
    float acc[2][4][4])
{
    // 512 threads: 1 cp16 for A + 1 cp16 for B per thread per kt
#define PREF(kt, st) do {                                                   \
        uint32_t db = dst0 + (uint32_t)(st) * STAGE_B;                      \
        cp16(db,          pA + (kt) * 32);                                  \
        cp16(db + TILE_B, pB + (kt) * 32);                                  \
        cp_commit();                                                        \
    } while (0)

    PREF(0, 0);
    PREF(1, 1);
    for (int kt = 0; kt < KT32; kt++) {
        const int st = kt % 3;
        if (kt + 2 < KT32)      { PREF(kt + 2, (kt + 2) % 3); cpwait<2>(); }
        else if (kt + 1 < KT32) { cpwait<1>(); }
        else                    { cpwait<0>(); }
        __syncthreads();

        const uint32_t sb = (uint32_t)st * STAGE_B;
#pragma unroll
        for (int kk = 0; kk < 2; kk++) {
            const uint32_t ko = sb + kk * 32;
            uint32_t a[2][4], b[4][2];
            ldm_x4(a[0], aoff + ko);
            ldm_x4(a[1], aoff + ko + 16 * SSTRIDE * 2);
#pragma unroll
            for (int ng = 0; ng < 2; ng++) {
                uint32_t r[4];
                ldm_x4(r, boff + ko + ng * 16 * SSTRIDE * 2);
                b[2 * ng][0] = r[0]; b[2 * ng][1] = r[2];
                b[2 * ng + 1][0] = r[1]; b[2 * ng + 1][1] = r[3];
            }
#pragma unroll
            for (int mt = 0; mt < 2; mt++)
#pragma unroll
                for (int nt = 0; nt < 4; nt++)
                    mma_h(acc[mt][nt], a[mt], b[nt][0], b[nt][1]);
        }
        __syncthreads();
    }
#undef PREF
}

// fused QKV: z selects weight + fp16 output
__global__ __launch_bounds__(512, 1)
void gemm_qkv(const __half* __restrict__ A,
              const __half* __restrict__ W0, const __half* __restrict__ W1,
              const __half* __restrict__ W2,
              __half* __restrict__ O0, __half* __restrict__ O1,
              __half* __restrict__ O2)
{
    extern __shared__ __half smemh[];
    const uint32_t smem = smem_u32(smemh);
    const int tid = threadIdx.x, lane = tid & 31, w = tid >> 5;
    const int m0 = blockIdx.y * 128, n0 = blockIdx.x * 128;
    const __half* Bm = (blockIdx.z == 0) ? W0 : (blockIdx.z == 1 ? W1 : W2);
    __half* C = (blockIdx.z == 0) ? O0 : (blockIdx.z == 1 ? O1 : O2);

    // loader: row = tid>>2 (0..127), col chunk = (tid&3)*8 halfs
    const int lr = tid >> 2, lc = (tid & 3) * 8;
    const __half* pA = A  + (size_t)(m0 + lr) * DIMN + lc;
    const __half* pB = Bm + (size_t)(n0 + lr) * DIMN + lc;
    const uint32_t dst0 = smem + (uint32_t)(lr * SSTRIDE + lc) * 2;

    // compute: 16 warps = 4 (M) x 4 (N), warptile 32x32
    const int wm = w & 3, wn = w >> 2;
    const uint32_t aoff = smem +
        (uint32_t)((wm * 32 + (lane & 15)) * SSTRIDE + (lane >> 4) * 8) * 2;
    const uint32_t boff = smem + TILE_B +
        (uint32_t)((wn * 32 + (lane & 15)) * SSTRIDE + (lane >> 4) * 8) * 2;

    float acc[2][4][4];
#pragma unroll
    for (int i = 0; i < 2; i++)
#pragma unroll
        for (int j = 0; j < 4; j++)
#pragma unroll
            for (int t = 0; t < 4; t++) acc[i][j][t] = 0.f;

    gemm_core(pA, pB, dst0, aoff, boff, acc);

    const int gr = lane >> 2, gc = (lane & 3) * 2;
#pragma unroll
    for (int mt = 0; mt < 2; mt++) {
        const int row = m0 + wm * 32 + mt * 16 + gr;
#pragma unroll
        for (int nt = 0; nt < 4; nt++) {
            const int col = n0 + wn * 32 + nt * 8 + gc;
            *(__half2*)(C + (size_t)row * DIMN + col) =
                __floats2half2_rn(acc[mt][nt][0], acc[mt][nt][1]);
            *(__half2*)(C + (size_t)(row + 8) * DIMN + col) =
                __floats2half2_rn(acc[mt][nt][2], acc[mt][nt][3]);
        }
    }
}

// final GEMM: fp32 out + bias
__global__ __launch_bounds__(512, 1)
void gemm_out(const __half* __restrict__ A, const __half* __restrict__ Bm,
              const float* __restrict__ bias, float* __restrict__ C)
{
    extern __shared__ __half smemh[];
    const uint32_t smem = smem_u32(smemh);
    const int tid = threadIdx.x, lane = tid & 31, w = tid >> 5;
    const int m0 = blockIdx.y * 128, n0 = blockIdx.x * 128;

    const int lr = tid >> 2, lc = (tid & 3) * 8;
    const __half* pA = A  + (size_t)(m0 + lr) * DIMN + lc;
    const __half* pB = Bm + (size_t)(n0 + lr) * DIMN + lc;
    const uint32_t dst0 = smem + (uint32_t)(lr * SSTRIDE + lc) * 2;

    const int wm = w & 3, wn = w >> 2;
    const uint32_t aoff = smem +
        (uint32_t)((wm * 32 + (lane & 15)) * SSTRIDE + (lane >> 4) * 8) * 2;
    const uint32_t boff = smem + TILE_B +
        (uint32_t)((wn * 32 + (lane & 15)) * SSTRIDE + (lane >> 4) * 8) * 2;

    float acc[2][4][4];
#pragma unroll
    for (int i = 0; i < 2; i++)
#pragma unroll
        for (int j = 0; j < 4; j++)
#pragma unroll
            for (int t = 0; t < 4; t++) acc[i][j][t] = 0.f;

    gemm_core(pA, pB, dst0, aoff, boff, acc);

    const int gr = lane >> 2, gc = (lane & 3) * 2;
#pragma unroll
    for (int mt = 0; mt < 2; mt++) {
        const int row = m0 + wm * 32 + mt * 16 + gr;
#pragma unroll
        for (int nt = 0; nt < 4; nt++) {
            const int col = n0 + wn * 32 + nt * 8 + gc;
            const float b0 = bias[col], b1 = bias[col + 1];
            *(float2*)(C + (size_t)row * DIMN + col) =
                make_float2(acc[mt][nt][0] + b0, acc[mt][nt][1] + b1);
            *(float2*)(C + (size_t)(row + 8) * DIMN + col) =
                make_float2(acc[mt][nt][2] + b0, acc[mt][nt][3] + b1);
        }
    }
}

// ---------------------------------------------------------------------------
// HMMA block-local attention + fused global attention (proven R7 version).
// One CTA per (b, blk, head), 8 warps x 16 query rows (warp 7 takes tile 8).
// ---------------------------------------------------------------------------
#define AQS 72                               // smem row stride (halfs)
#define HQ  (144 * AQS)                      // halfs per tile
#define GK_OFF (3 * HQ)
#define GV_OFF (GK_OFF + 32 * AQS)
#define GP_BYTE ((GV_OFF + 32 * AQS) * 2)
#define GOUT_BYTE (GP_BYTE + 32 * 4)
#define AT_SMEM (GOUT_BYTE + 64 * 4)         // 71808 B

__global__ __launch_bounds__(256, 2)
void blk_attn_tc(const __half* __restrict__ q16, const __half* __restrict__ k16,
                 const __half* __restrict__ v16, __half* __restrict__ a16)
{
    extern __shared__ __half sh[];
    __half* Qs = sh;
    __half* Ks = sh + HQ;
    __half* Vs = sh + 2 * HQ;
    __half* gk = sh + GK_OFF;
    __half* gv = sh + GV_OFF;
    float* gp   = (float*)((char*)sh + GP_BYTE);
    float* gout = (float*)((char*)sh + GOUT_BYTE);

    const int bid = blockIdx.x;
    const int h = bid & 15, blk = (bid >> 4) & 31, b = bid >> 9;
    const size_t gbase = ((size_t)(b * NLEN + blk * BLKLEN)) * DIMN + h * DK;
    const int tid = threadIdx.x, lane = tid & 31, wid = tid >> 5;

    const uint4 z4 = make_uint4(0, 0, 0, 0);
    for (int i = tid; i < 360; i += 256) {
        const int t = i / 120, j = i % 120;
        const int r = 129 + (j >> 3), c = (j & 7) * 8;
        __half* base = (t == 0) ? Qs : (t == 1) ? Ks : Vs;
        *(uint4*)&base[r * AQS + c] = z4;
    }
    for (int i = tid; i < 1032; i += 256) {
        const int r = i >> 3, c = (i & 7) * 8;
        const uint32_t so = (uint32_t)(r * AQS + c) * 2;
        const size_t g = gbase + (size_t)r * DIMN + c;
        cp16(smem_u32(Qs) + so, q16 + g);
        cp16(smem_u32(Ks) + so, k16 + g);
        cp16(smem_u32(Vs) + so, v16 + g);
    }
    {
        const int r = tid >> 3, c = (tid & 7) * 8;
        const size_t g = ((size_t)(b * NLEN + r * BLKLEN)) * DIMN + h * DK + c;
        const uint32_t so = (uint32_t)(r * AQS + c) * 2;
        cp16(smem_u32(gk) + so, k16 + g);
        cp16(smem_u32(gv) + so, v16 + g);
    }
    cp_commit();
    cpwait<0>();
    __syncthreads();

    const float scale = 0.125f;

    // warp 0: global attention for this block's first token
    if (wid == 0) {
        float s = 0.f;
#pragma unroll
        for (int i = 0; i < DK / 2; i++) {
            float2 qf = __half22float2(*(const __half2*)&Qs[2 * i]);
            float2 kf = __half22float2(*(const __half2*)&gk[lane * AQS + 2 * i]);
            s += qf.x * kf.x + qf.y * kf.y;
        }
        float p = __expf(s * scale);
        float lsum = p;
#pragma unroll
        for (int d = 1; d < 32; d <<= 1)
            lsum += __shfl_xor_sync(0xFFFFFFFFu, lsum, d);
        gp[lane] = p;
        __syncwarp();
        const float inv = 1.0f / lsum;
        float o0 = 0.f, o1 = 0.f;
#pragma unroll
        for (int k = 0; k < NB; k++) {
            const float pk = gp[k];
            float2 vf = __half22float2(*(const __half2*)&gv[k * AQS + 2 * lane]);
            o0 += pk * vf.x; o1 += pk * vf.y;
        }
        gout[2 * lane]     = o0 * inv;
        gout[2 * lane + 1] = o1 * inv;
        __syncwarp();
    }

    const int cbase = (lane & 3) * 2;
    const int gr = lane >> 2;
    const uint32_t loff = (uint32_t)((lane & 15) * AQS + (lane >> 4) * 8) * 2;
    const int vmat = lane >> 3;
    const uint32_t vb = smem_u32(Vs) +
        (uint32_t)(((vmat & 1) * 8 + (lane & 7)) * AQS + (vmat >> 1) * 8) * 2;

    const int niter = (wid == 7) ? 2 : 1;
    for (int it = 0; it < niter; it++) {
        const int t = (it == 0) ? wid : 8;
        const int m0 = t * 16;

        uint32_t aq[4][4];
        {
            const uint32_t qb = smem_u32(Qs) + (uint32_t)(m0 * AQS) * 2 + loff;
#pragma unroll
            for (int ks = 0; ks < 4; ks++) ldm_x4(aq[ks], qb + ks * 32);
        }

        uint32_t P2[17][2];
        float l0 = 0.f, l1 = 0.f;
        const uint32_t kb = smem_u32(Ks) + loff;
#pragma unroll
        for (int jp = 0; jp < 8; jp++) {
            float e0[4] = {0.f, 0.f, 0.f, 0.f};
            float e1[4] = {0.f, 0.f, 0.f, 0.f};
            const uint32_t kjb = kb + (uint32_t)(jp * 16 * AQS) * 2;
#pragma unroll
            for (int ks = 0; ks < 4; ks++) {
                uint32_t r[4];
                ldm_x4(r, kjb + ks * 32);
                mma_h(e0, aq[ks], r[0], r[2]);
                mma_h(e1, aq[ks], r[1], r[3]);
            }
            float p00 = __expf(e0[0] * scale), p01 = __expf(e0[1] * scale);
            float p02 = __expf(e0[2] * scale), p03 = __expf(e0[3] * scale);
            float p10 = __expf(e1[0] * scale), p11 = __expf(e1[1] * scale);
            float p12 = __expf(e1[2] * scale), p13 = __expf(e1[3] * scale);
            l0 += (p00 + p01) + (p10 + p11);
            l1 += (p02 + p03) + (p12 + p13);
            P2[2 * jp][0] = packh2(p00, p01);
            P2[2 * jp][1] = packh2(p02, p03);
            P2[2 * jp + 1][0] = packh2(p10, p11);
            P2[2 * jp + 1][1] = packh2(p12, p13);
        }
        {
            float e0[4] = {0.f, 0.f, 0.f, 0.f};
            const uint32_t kjb = kb + (uint32_t)(128 * AQS) * 2;
#pragma unroll
            for (int ks = 0; ks < 4; ks++) {
                uint32_t r[4];
                ldm_x4(r, kjb + ks * 32);
                mma_h(e0, aq[ks], r[0], r[2]);
            }
            const bool v = (cbase == 0);
            float p0 = v ? __expf(e0[0] * scale) : 0.f;
            float p2 = v ? __expf(e0[2] * scale) : 0.f;
            l0 += p0; l1 += p2;
            P2[16][0] = packh2(p0, 0.f);
            P2[16][1] = packh2(p2, 0.f);
        }
        l0 += __shfl_xor_sync(0xFFFFFFFFu, l0, 1);
        l0 += __shfl_xor_sync(0xFFFFFFFFu, l0, 2);
        l1 += __shfl_xor_sync(0xFFFFFFFFu, l1, 1);
        l1 += __shfl_xor_sync(0xFFFFFFFFu, l1, 2);

        float oacc[8][4];
#pragma unroll
        for (int g = 0; g < 8; g++)
#pragma unroll
            for (int u = 0; u < 4; u++) oacc[g][u] = 0.f;

#pragma unroll
        for (int kp = 0; kp < 9; kp++) {
            uint32_t pa[4];
            pa[0] = P2[2 * kp][0];
            pa[1] = P2[2 * kp][1];
            if (kp < 8) { pa[2] = P2[2 * kp + 1][0]; pa[3] = P2[2 * kp + 1][1]; }
            else        { pa[2] = 0u; pa[3] = 0u; }
            const uint32_t vkb = vb + (uint32_t)(kp * 16 * AQS) * 2;
#pragma unroll
            for (int g = 0; g < 4; g++) {
                uint32_t r[4];
                ldm_x4_t(r, vkb + g * 32);
                mma_h(oacc[2 * g],     pa, r[0], r[1]);
                mma_h(oacc[2 * g + 1], pa, r[2], r[3]);
            }
        }

        const float rl0 = 1.0f / l0, rl1 = 1.0f / l1;
        const int r0 = m0 + gr, r1 = r0 + 8;
#pragma unroll
        for (int g = 0; g < 8; g++) {
            const int col = g * 8 + cbase;
            float o0 = oacc[g][0] * rl0, o1 = oacc[g][1] * rl0;
            float o2 = oacc[g][2] * rl1, o3 = oacc[g][3] * rl1;
            if (r0 == 0) { o0 += gout[col]; o1 += gout[col + 1]; }
            if (r0 < BLKLEN)
                *(__half2*)(a16 + gbase + (size_t)r0 * DIMN + col) =
                    __floats2half2_rn(o0, o1);
            if (r1 < BLKLEN)
                *(__half2*)(a16 + gbase + (size_t)r1 * DIMN + col) =
                    __floats2half2_rn(o2, o3);
        }
    }
}

// ---------------------------------------------------------------------------
extern "C" void kernel_launch(void* const* d_in, const int* in_sizes, int n_in,
                              void* d_out, int out_size)
{
    const float* x  = (const float*)d_in[0];
    const float* Wq = (const float*)d_in[1];
    const float* Wk = (const float*)d_in[2];
    const float* Wv = (const float*)d_in[3];
    const float* Wo = (const float*)d_in[4];
    const float* bo = (const float*)d_in[5];
    float* out = (float*)d_out;

    __half *x16, *q16, *k16, *v16, *a16, *w16;
    cudaGetSymbolAddress((void**)&x16, g_x16);
    cudaGetSymbolAddress((void**)&q16, g_q16);
    cudaGetSymbolAddress((void**)&k16, g_k16);
    cudaGetSymbolAddress((void**)&v16, g_v16);
    cudaGetSymbolAddress((void**)&a16, g_a16);
    cudaGetSymbolAddress((void**)&w16, g_w16);

    cudaFuncSetAttribute(gemm_qkv, cudaFuncAttributeMaxDynamicSharedMemorySize, GEMM_SMEM);
    cudaFuncSetAttribute(gemm_out, cudaFuncAttributeMaxDynamicSharedMemorySize, GEMM_SMEM);
    cudaFuncSetAttribute(blk_attn_tc, cudaFuncAttributeMaxDynamicSharedMemorySize, AT_SMEM);

    const int W = DIMN * DIMN;
    const int n16x = TOK * DIMN / 16;
    const int n16w = W / 16;

    cvt_h16<<<(n16x + 255) / 256, 256>>>((const float4*)x, (uint4*)x16, n16x);
    dim3 gW((n16w + 255) / 256, 4);
    cvt_w16<<<gW, 256>>>((const float4*)Wq, (const float4*)Wk,
                         (const float4*)Wv, (const float4*)Wo,
                         (uint4*)w16, n16w);

    dim3 gQKV(DIMN / 128, TOK / 128, 3);   // (8, 129, 3)
    gemm_qkv<<<gQKV, 512, GEMM_SMEM>>>(x16,
        w16 + 0 * W, w16 + 1 * W, w16 + 2 * W, q16, k16, v16);

    blk_attn_tc<<<B_SZ * NB * HEADS, 256, AT_SMEM>>>(q16, k16, v16, a16);

    dim3 gO(DIMN / 128, TOK / 128);        // (8, 129)
    gemm_out<<<gO, 512, GEMM_SMEM>>>(a16, w16 + 3 * W, bo, out);
}